// round 7
// baseline (speedup 1.0000x reference)
#include <cuda_runtime.h>

// ---------------------------------------------------------------------------
// LeNet-5 forward, B=8192, fp32, FFMA2 (fma.rn.f32x2) packed math.
//   prep : pooled-effective 6x6 filters (conv5x5+avgpool fused), slopes folded
//   K12  : C1+S2+act then C3+S4+act (dense, masked weights pre-zeroed)
//   K3   : C5 (+bias) -> C[8192][480]
//   K4   : F6+act+RBF -> out[32768][10]
// ---------------------------------------------------------------------------

#define ACT_SCALE 1.7159f
#define ACT_SLOPE (2.0f / 3.0f)

typedef unsigned long long u64;

__device__ __forceinline__ u64 pk2(float lo, float hi) {
    u64 r; asm("mov.b64 %0, {%1, %2};" : "=l"(r) : "f"(lo), "f"(hi)); return r;
}
__device__ __forceinline__ void fma2(u64& d, u64 a, u64 b) {
    asm("fma.rn.f32x2 %0, %1, %2, %0;" : "+l"(d) : "l"(a), "l"(b));
}
__device__ __forceinline__ float hsum2(u64 v) {
    float lo, hi; asm("mov.b64 {%0, %1}, %2;" : "=f"(lo), "=f"(hi) : "l"(v));
    return lo + hi;
}
__device__ __forceinline__ float fast_tanh(float x) {
    float e = __expf(2.0f * x);
    return 1.0f - __fdividef(2.0f, e + 1.0f);
}

// bit i of c_cmask[o] set iff input channel i feeds output channel o (MAP_INFO)
static __constant__ unsigned c_cmask[16] = {
    7u, 14u, 28u, 56u, 49u, 35u, 15u, 30u,
    60u, 57u, 51u, 39u, 27u, 54u, 45u, 63u
};

// Scratch (module-static device memory; no runtime allocation)
__device__ float g_B[8192 * 16 * 6 * 6];
__device__ float g_C[8192 * 480];
__device__ __align__(16) float g_w6c1[6 * 36];
__device__ float g_bf1[6];
__device__ __align__(16) float g_w6c3[16 * 6 * 36];
__device__ float g_bf3[16];

// ---------------------------------------------------------------------------
__global__ void k_prep(const float* __restrict__ c1_w, const float* __restrict__ c1_b,
                       const float* __restrict__ s2_w, const float* __restrict__ s2_b,
                       const float* __restrict__ c3_w, const float* __restrict__ c3_b,
                       const float* __restrict__ s4_w, const float* __restrict__ s4_b) {
    int t = threadIdx.x;
    for (int idx = t; idx < 216; idx += 256) {
        int c = idx / 36, a = (idx % 36) / 6, b = idx % 6;
        float s = 0.f;
        #pragma unroll
        for (int di = 0; di < 2; di++)
            #pragma unroll
            for (int dj = 0; dj < 2; dj++) {
                int u = a - di, v = b - dj;
                if (u >= 0 && u < 5 && v >= 0 && v < 5)
                    s += c1_w[(c * 5 + u) * 5 + v];
            }
        g_w6c1[idx] = 0.25f * ACT_SLOPE * s2_w[c] * s;
    }
    if (t < 6) g_bf1[t] = ACT_SLOPE * (s2_w[t] * c1_b[t] + s2_b[t]);
    for (int idx = t; idx < 3456; idx += 256) {
        int o = idx / 216;
        int i = (idx % 216) / 36;
        int ab = idx % 36;
        int a = ab / 6, b = ab % 6;
        float s = 0.f;
        #pragma unroll
        for (int di = 0; di < 2; di++)
            #pragma unroll
            for (int dj = 0; dj < 2; dj++) {
                int u = a - di, v = b - dj;
                if (u >= 0 && u < 5 && v >= 0 && v < 5)
                    s += c3_w[((o * 6 + i) * 5 + u) * 5 + v];
            }
        float m = ((c_cmask[o] >> i) & 1u) ? 1.f : 0.f;
        g_w6c3[idx] = m * 0.25f * ACT_SLOPE * s4_w[o] * s;
    }
    if (t < 16) g_bf3[t] = ACT_SLOPE * (s4_w[t] * c3_b[t] + s4_b[t]);
}

// ---------------------------------------------------------------------------
// K12: fused C1+S2+act and C3+S4+act.  4 images/block, 192 threads.
// FFMA2 packed over the s (kernel column) dimension; partial even/odd sums.
// ---------------------------------------------------------------------------
#define K12_IMG 4
#define K12_THREADS 192

__global__ void __launch_bounds__(K12_THREADS) k12(const float* __restrict__ x) {
    __shared__ __align__(16) float sin[K12_IMG][1296];
    __shared__ __align__(16) float sA[K12_IMG][1536];
    __shared__ __align__(16) float sw1[216];
    __shared__ __align__(16) float sw3[3456];
    __shared__ float sb1[6];
    __shared__ float sb3[16];
    int t = threadIdx.x;
    long img0 = (long)blockIdx.x * K12_IMG;

    for (int idx = t; idx < 216; idx += K12_THREADS) sw1[idx] = g_w6c1[idx];
    for (int idx = t; idx < 3456; idx += K12_THREADS) sw3[idx] = g_w6c3[idx];
    if (t < 6) sb1[t] = g_bf1[t];
    if (t < 16) sb3[t] = g_bf3[t];
    for (int idx = t; idx < K12_IMG * 1296; idx += K12_THREADS) {
        int m = idx / 1296, p = idx % 1296;
        int r = p / 36, c = p % 36;
        int sr = min(max(r - 2, 0), 31);
        int sc = min(max(c - 2, 0), 31);
        sin[m][p] = x[(img0 + m) * 1024 + sr * 32 + sc];
    }
    __syncthreads();

    // ---- C1+S2+act ----
    {
        int pr = t >> 3;          // 0..23 = img*6 + ch
        int q = t & 7;
        int img = pr / 6, ch = pr % 6;
        float4 w4[9];
        float* w = (float*)w4;
        #pragma unroll
        for (int v = 0; v < 9; v++)
            w4[v] = ((const float4*)(sw1 + ch * 36))[v];
        u64 wp[6][3];
        #pragma unroll
        for (int r = 0; r < 6; r++)
            #pragma unroll
            for (int j = 0; j < 3; j++)
                wp[r][j] = pk2(w[r * 6 + 2 * j], w[r * 6 + 2 * j + 1]);
        float bias = sb1[ch];
        #pragma unroll
        for (int tl = 0; tl < 8; tl++) {
            const float* bp = &sin[img][0] + (4 * tl) * 36 + 4 * q;
            u64 a00 = 0, a01 = 0, a10 = 0, a11 = 0;
            #pragma unroll
            for (int row = 0; row < 8; row++) {
                u64 rp[4];
                #pragma unroll
                for (int h = 0; h < 4; h++)
                    rp[h] = *(const u64*)(bp + row * 36 + 2 * h);
                if (row < 6) {
                    #pragma unroll
                    for (int j = 0; j < 3; j++) {
                        fma2(a00, wp[row][j], rp[j]);
                        fma2(a01, wp[row][j], rp[j + 1]);
                    }
                }
                if (row >= 2) {
                    #pragma unroll
                    for (int j = 0; j < 3; j++) {
                        fma2(a10, wp[row - 2][j], rp[j]);
                        fma2(a11, wp[row - 2][j], rp[j + 1]);
                    }
                }
            }
            float* op = &sA[img][ch * 256 + (2 * tl) * 16 + 2 * q];
            op[0]  = ACT_SCALE * fast_tanh(hsum2(a00) + bias);
            op[1]  = ACT_SCALE * fast_tanh(hsum2(a01) + bias);
            op[16] = ACT_SCALE * fast_tanh(hsum2(a10) + bias);
            op[17] = ACT_SCALE * fast_tanh(hsum2(a11) + bias);
        }
    }
    __syncthreads();

    // ---- C3+S4+act (dense; masked weights are zero) ----
    {
        int pr = t / 3;           // 0..63 = img*16 + och
        int q = t % 3;
        int img = pr >> 4, och = pr & 15;
        float bias = sb3[och];
        u64 acc[3][4];
        #pragma unroll
        for (int u = 0; u < 3; u++)
            #pragma unroll
            for (int v = 0; v < 4; v++) acc[u][v] = 0;
        int ti_[3], tj_[3];
        #pragma unroll
        for (int u = 0; u < 3; u++) {
            int tile = q + u * 3;
            ti_[u] = tile / 3;
            tj_[u] = tile % 3;
        }
        for (int ic = 0; ic < 6; ic++) {
            float4 w4[9];
            float* w = (float*)w4;
            #pragma unroll
            for (int v = 0; v < 9; v++)
                w4[v] = ((const float4*)(sw3 + och * 216 + ic * 36))[v];
            u64 wp[6][3];
            #pragma unroll
            for (int r = 0; r < 6; r++)
                #pragma unroll
                for (int j = 0; j < 3; j++)
                    wp[r][j] = pk2(w[r * 6 + 2 * j], w[r * 6 + 2 * j + 1]);
            #pragma unroll
            for (int u = 0; u < 3; u++) {
                const float* bp = &sA[img][ic * 256 + (4 * ti_[u]) * 16 + 4 * tj_[u]];
                #pragma unroll
                for (int row = 0; row < 8; row++) {
                    u64 rp[4];
                    #pragma unroll
                    for (int h = 0; h < 4; h++)
                        rp[h] = *(const u64*)(bp + row * 16 + 2 * h);
                    if (row < 6) {
                        #pragma unroll
                        for (int j = 0; j < 3; j++) {
                            fma2(acc[u][0], wp[row][j], rp[j]);
                            fma2(acc[u][1], wp[row][j], rp[j + 1]);
                        }
                    }
                    if (row >= 2) {
                        #pragma unroll
                        for (int j = 0; j < 3; j++) {
                            fma2(acc[u][2], wp[row - 2][j], rp[j]);
                            fma2(acc[u][3], wp[row - 2][j], rp[j + 1]);
                        }
                    }
                }
            }
        }
        float* ob = g_B + (img0 + img) * 576 + och * 36;
        #pragma unroll
        for (int u = 0; u < 3; u++) {
            int r0 = 2 * ti_[u], c0 = 2 * tj_[u];
            ob[r0 * 6 + c0]           = ACT_SCALE * fast_tanh(hsum2(acc[u][0]) + bias);
            ob[r0 * 6 + c0 + 1]       = ACT_SCALE * fast_tanh(hsum2(acc[u][1]) + bias);
            ob[(r0 + 1) * 6 + c0]     = ACT_SCALE * fast_tanh(hsum2(acc[u][2]) + bias);
            ob[(r0 + 1) * 6 + c0 + 1] = ACT_SCALE * fast_tanh(hsum2(acc[u][3]) + bias);
        }
    }
}

// ---------------------------------------------------------------------------
// K3: C5 16->120 conv5x5 on 6x6 -> 4 positions (+bias).
// 20 images/block, 160 threads, 32-ch weight chunks.
// Weights in smem per-channel-major [32][482]; each 5-tap row padded to 6
// (slot s=5 zero) so k-pairs are 8B-aligned.  FFMA2 over k-pairs; patch
// cached in regs (padded to 40 so the (pj=1,s=4) pair stays in-bounds).
// ---------------------------------------------------------------------------
#define K3_IMG 20
#define K3_CH  32
#define K3_THREADS 160
#define K3_INSTRIDE 584
#define K3_WSTRIDE  482
#define K3_SMEM ((K3_IMG * K3_INSTRIDE + K3_CH * K3_WSTRIDE) * 4)
#define K3_GRID ((8192 + K3_IMG - 1) / K3_IMG)

__global__ void __launch_bounds__(K3_THREADS) k3(const float* __restrict__ c5_w,
                                                 const float* __restrict__ c5_b) {
    extern __shared__ __align__(16) float sm3[];
    float* sin = sm3;                         // [20][584]
    float* swt = sm3 + K3_IMG * K3_INSTRIDE;  // [32][482]
    int t = threadIdx.x;
    long imgbase = (long)blockIdx.x * K3_IMG;
    for (int idx = t; idx < K3_IMG * 576; idx += K3_THREADS) {
        int im = idx / 576, off = idx % 576;
        long gi = imgbase + im;
        sin[im * K3_INSTRIDE + off] = (gi < 8192) ? g_B[gi * 576 + off] : 0.f;
    }
    int cg = t & 7;   // channel group (4 channels each)
    int pg = t >> 3;  // local image index 0..19
    const float* ip = sin + pg * K3_INSTRIDE;
    long gimg = imgbase + pg;
    float* outp = g_C + gimg * 480;

    for (int chunk = 0; chunk < 120; chunk += K3_CH) {
        __syncthreads();
        for (int idx = t; idx < K3_CH * K3_WSTRIDE; idx += K3_THREADS) {
            int ch = idx / K3_WSTRIDE, kp = idx % K3_WSTRIDE;
            float wv = 0.f;
            if (kp < 480) {
                int s = kp % 6, rr = kp / 6;    // rr = ic*5+r
                int gch = chunk + ch;
                if (s < 5 && gch < 120)
                    wv = c5_w[(long)gch * 400 + rr * 5 + s];
            }
            swt[idx] = wv;
        }
        __syncthreads();

        u64 acc[4][4];
        #pragma unroll
        for (int p = 0; p < 4; p++)
            #pragma unroll
            for (int c = 0; c < 4; c++) acc[p][c] = 0;

        for (int ic = 0; ic < 16; ic++) {
            float4 pv4[10];
            float* pv = (float*)pv4;
            #pragma unroll
            for (int v = 0; v < 9; v++)
                pv4[v] = ((const float4*)(ip + ic * 36))[v];
            pv4[9] = make_float4(0.f, 0.f, 0.f, 0.f);
            #pragma unroll
            for (int r = 0; r < 5; r++) {
                u64 vp[4][3];
                #pragma unroll
                for (int pi = 0; pi < 2; pi++)
                    #pragma unroll
                    for (int pj = 0; pj < 2; pj++) {
                        int b = (pi + r) * 6 + pj;
                        #pragma unroll
                        for (int jj = 0; jj < 3; jj++)
                            vp[pi * 2 + pj][jj] = pk2(pv[b + 2 * jj], pv[b + 2 * jj + 1]);
                    }
                int wrow = (ic * 5 + r) * 6;
                #pragma unroll
                for (int cc = 0; cc < 4; cc++) {
                    const float* wc = swt + (cg * 4 + cc) * K3_WSTRIDE + wrow;
                    #pragma unroll
                    for (int jj = 0; jj < 3; jj++) {
                        u64 wpair = *(const u64*)(wc + 2 * jj);
                        #pragma unroll
                        for (int p = 0; p < 4; p++)
                            fma2(acc[p][cc], wpair, vp[p][jj]);
                    }
                }
            }
        }
        if (gimg < 8192) {
            #pragma unroll
            for (int cc = 0; cc < 4; cc++) {
                int ch = chunk + cg * 4 + cc;
                if (ch < 120) {
                    float b = c5_b[ch];
                    float4 o;
                    o.x = hsum2(acc[0][cc]) + b;
                    o.y = hsum2(acc[1][cc]) + b;
                    o.z = hsum2(acc[2][cc]) + b;
                    o.w = hsum2(acc[3][cc]) + b;
                    *(float4*)(outp + ch * 4) = o;
                }
            }
        }
    }
}

// ---------------------------------------------------------------------------
// K4: F6 (120->84) + act + RBF.  View C as [32768][120]; 64 rows/block.
// Weights kept n-major [84][122] so k-pairs are adjacent; FFMA2 over k.
// sh overlays srow (after a barrier) -> smem 75.9 KB -> 3 CTAs/SM.
// ---------------------------------------------------------------------------
#define K4_ROWS 64
#define K4_SMEM ((K4_ROWS * 122 + 84 * 122 + 840 + 84) * 4)

__global__ void __launch_bounds__(256) k4(const float* __restrict__ f6_w,
                                          const float* __restrict__ f6_b,
                                          const float* __restrict__ rbf_w,
                                          float* __restrict__ out) {
    extern __shared__ __align__(16) float sm4[];
    float* srow = sm4;                   // [64][122]; later overlaid by sh [64][85]
    float* swt  = srow + K4_ROWS * 122;  // [84][122]  (n-major, pre-scaled)
    float* srbf = swt + 84 * 122;        // [84][10]
    float* sb6  = srbf + 840;            // [84]
    float* sh   = srow;                  // overlay
    int t = threadIdx.x, blk = blockIdx.x;
    long row0 = (long)blk * K4_ROWS;

    for (int idx = t; idx < K4_ROWS * 120; idx += 256) {
        int r = idx / 120, k = idx % 120;
        srow[r * 122 + k] = g_C[(row0 + r) * 120 + k];
    }
    for (int idx = t; idx < 84 * 120; idx += 256) {
        int n = idx / 120, k = idx % 120;
        swt[n * 122 + k] = ACT_SLOPE * f6_w[idx];
    }
    for (int idx = t; idx < 840; idx += 256) srbf[idx] = rbf_w[idx];
    if (t < 84) sb6[t] = ACT_SLOPE * f6_b[t];
    __syncthreads();

    int rg = t >> 4;    // 16 row-groups of 4 rows
    int cl = t & 15;    // column lane: cols cl, cl+16, ...
    u64 acc[4][6];
    #pragma unroll
    for (int i = 0; i < 4; i++)
        #pragma unroll
        for (int q = 0; q < 6; q++) acc[i][q] = 0;

    const float* r0 = srow + (rg * 4 + 0) * 122;
    const float* r1 = srow + (rg * 4 + 1) * 122;
    const float* r2 = srow + (rg * 4 + 2) * 122;
    const float* r3 = srow + (rg * 4 + 3) * 122;
    for (int k = 0; k < 120; k += 2) {
        u64 v0 = *(const u64*)(r0 + k);
        u64 v1 = *(const u64*)(r1 + k);
        u64 v2 = *(const u64*)(r2 + k);
        u64 v3 = *(const u64*)(r3 + k);
        #pragma unroll
        for (int q = 0; q < 6; q++) {
            int n = cl + 16 * q;
            if (n < 84) {
                u64 w = *(const u64*)(swt + n * 122 + k);
                fma2(acc[0][q], v0, w);
                fma2(acc[1][q], v1, w);
                fma2(acc[2][q], v2, w);
                fma2(acc[3][q], v3, w);
            }
        }
    }
    float hv[4][6];
    #pragma unroll
    for (int q = 0; q < 6; q++) {
        int n = cl + 16 * q;
        if (n < 84) {
            float bias = sb6[n];
            #pragma unroll
            for (int i = 0; i < 4; i++)
                hv[i][q] = ACT_SCALE * fast_tanh(hsum2(acc[i][q]) + bias);
        }
    }
    __syncthreads();   // all reads of srow done before sh overlay writes
    #pragma unroll
    for (int q = 0; q < 6; q++) {
        int n = cl + 16 * q;
        if (n < 84) {
            #pragma unroll
            for (int i = 0; i < 4; i++)
                sh[(rg * 4 + i) * 85 + n] = hv[i][q];
        }
    }
    __syncthreads();

    for (int idx = t; idx < K4_ROWS * 10; idx += 256) {
        int r = idx / 10, o = idx % 10;
        const float* hr = sh + r * 85;
        float s = 0.f;
        #pragma unroll 4
        for (int n = 0; n < 84; n++) {
            float d = hr[n] - srbf[n * 10 + o];
            s = fmaf(d, d, s);
        }
        out[(row0 + r) * 10 + o] = s;
    }
}

// ---------------------------------------------------------------------------
extern "C" void kernel_launch(void* const* d_in, const int* in_sizes, int n_in,
                              void* d_out, int out_size) {
    const float* x     = (const float*)d_in[0];
    const float* c1_w  = (const float*)d_in[1];
    const float* c1_b  = (const float*)d_in[2];
    const float* s2_w  = (const float*)d_in[3];
    const float* s2_b  = (const float*)d_in[4];
    const float* c3_w  = (const float*)d_in[5];
    const float* c3_b  = (const float*)d_in[6];
    const float* s4_w  = (const float*)d_in[7];
    const float* s4_b  = (const float*)d_in[8];
    const float* c5_w  = (const float*)d_in[9];
    const float* c5_b  = (const float*)d_in[10];
    const float* f6_w  = (const float*)d_in[11];
    const float* f6_b  = (const float*)d_in[12];
    const float* rbf_w = (const float*)d_in[13];

    cudaFuncSetAttribute(k3, cudaFuncAttributeMaxDynamicSharedMemorySize, K3_SMEM);
    cudaFuncSetAttribute(k4, cudaFuncAttributeMaxDynamicSharedMemorySize, K4_SMEM);

    k_prep<<<1, 256>>>(c1_w, c1_b, s2_w, s2_b, c3_w, c3_b, s4_w, s4_b);
    k12<<<8192 / K12_IMG, K12_THREADS>>>(x);
    k3<<<K3_GRID, K3_THREADS, K3_SMEM>>>(c5_w, c5_b);
    k4<<<32768 / K4_ROWS, 256, K4_SMEM>>>(f6_w, f6_b, rbf_w, (float*)d_out);
}

// round 8
// speedup vs baseline: 1.6240x; 1.6240x over previous
#include <cuda_runtime.h>

// ---------------------------------------------------------------------------
// LeNet-5 forward, B=8192, fp32.
//   prep : pooled-effective 6x6 filters (conv5x5+avgpool fused), slopes folded
//   K12  : C1+S2+act then C3+S4+act (dense, masked weights pre-zeroed),
//          8 images/block, 384 threads, register-tiled 2x2
//   K3   : C5 (+bias) -> C[8192][480]  (R6 version: reg patches + [400][33] W)
//   K4   : F6+act+RBF -> out[32768][10] (FFMA2 packed over k)
// ---------------------------------------------------------------------------

#define ACT_SCALE 1.7159f
#define ACT_SLOPE (2.0f / 3.0f)

typedef unsigned long long u64;

__device__ __forceinline__ void fma2(u64& d, u64 a, u64 b) {
    asm("fma.rn.f32x2 %0, %1, %2, %0;" : "+l"(d) : "l"(a), "l"(b));
}
__device__ __forceinline__ float hsum2(u64 v) {
    float lo, hi; asm("mov.b64 {%0, %1}, %2;" : "=f"(lo), "=f"(hi) : "l"(v));
    return lo + hi;
}
__device__ __forceinline__ float fast_tanh(float x) {
    float e = __expf(2.0f * x);
    return 1.0f - __fdividef(2.0f, e + 1.0f);
}

// bit i of c_cmask[o] set iff input channel i feeds output channel o (MAP_INFO)
static __constant__ unsigned c_cmask[16] = {
    7u, 14u, 28u, 56u, 49u, 35u, 15u, 30u,
    60u, 57u, 51u, 39u, 27u, 54u, 45u, 63u
};

// Scratch (module-static device memory; no runtime allocation)
__device__ float g_B[8192 * 16 * 6 * 6];
__device__ float g_C[8192 * 480];
__device__ __align__(16) float g_w6c1[6 * 36];
__device__ float g_bf1[6];
__device__ __align__(16) float g_w6c3[16 * 6 * 36];
__device__ float g_bf3[16];

// ---------------------------------------------------------------------------
__global__ void k_prep(const float* __restrict__ c1_w, const float* __restrict__ c1_b,
                       const float* __restrict__ s2_w, const float* __restrict__ s2_b,
                       const float* __restrict__ c3_w, const float* __restrict__ c3_b,
                       const float* __restrict__ s4_w, const float* __restrict__ s4_b) {
    int t = threadIdx.x;
    for (int idx = t; idx < 216; idx += 256) {
        int c = idx / 36, a = (idx % 36) / 6, b = idx % 6;
        float s = 0.f;
        #pragma unroll
        for (int di = 0; di < 2; di++)
            #pragma unroll
            for (int dj = 0; dj < 2; dj++) {
                int u = a - di, v = b - dj;
                if (u >= 0 && u < 5 && v >= 0 && v < 5)
                    s += c1_w[(c * 5 + u) * 5 + v];
            }
        g_w6c1[idx] = 0.25f * ACT_SLOPE * s2_w[c] * s;
    }
    if (t < 6) g_bf1[t] = ACT_SLOPE * (s2_w[t] * c1_b[t] + s2_b[t]);
    for (int idx = t; idx < 3456; idx += 256) {
        int o = idx / 216;
        int i = (idx % 216) / 36;
        int ab = idx % 36;
        int a = ab / 6, b = ab % 6;
        float s = 0.f;
        #pragma unroll
        for (int di = 0; di < 2; di++)
            #pragma unroll
            for (int dj = 0; dj < 2; dj++) {
                int u = a - di, v = b - dj;
                if (u >= 0 && u < 5 && v >= 0 && v < 5)
                    s += c3_w[((o * 6 + i) * 5 + u) * 5 + v];
            }
        float m = ((c_cmask[o] >> i) & 1u) ? 1.f : 0.f;
        g_w6c3[idx] = m * 0.25f * ACT_SLOPE * s4_w[o] * s;
    }
    if (t < 16) g_bf3[t] = ACT_SLOPE * (s4_w[t] * c3_b[t] + s4_b[t]);
}

// ---------------------------------------------------------------------------
// K12: fused C1+S2+act and C3+S4+act.  8 images/block, 384 threads.
// C1: thread = (img, ch) with weights in regs; 8 tiles of 2x2 outputs each.
// C3: thread = (img, och), dense over 6 in-ch; 3 tiles of 2x2 outputs each.
// Dynamic smem: sin[8][1296] | sA[8][1536] | sw1[216] | sw3[3456] | sb1/sb3.
// ---------------------------------------------------------------------------
#define K12_IMG 8
#define K12_THREADS 384
#define K12_SMEM ((K12_IMG * 1296 + K12_IMG * 1536 + 216 + 3456 + 8 + 16) * 4)

__global__ void __launch_bounds__(K12_THREADS) k12(const float* __restrict__ x) {
    extern __shared__ __align__(16) float sm12[];
    float* sinb = sm12;                        // [8][1296]
    float* sAb  = sinb + K12_IMG * 1296;       // [8][1536]
    float* sw1  = sAb + K12_IMG * 1536;        // [216]
    float* sw3  = sw1 + 216;                   // [3456]
    float* sb1  = sw3 + 3456;                  // [8] (6 used)
    float* sb3  = sb1 + 8;                     // [16]
    int t = threadIdx.x;
    long img0 = (long)blockIdx.x * K12_IMG;

    for (int idx = t; idx < 216; idx += K12_THREADS) sw1[idx] = g_w6c1[idx];
    for (int idx = t; idx < 3456; idx += K12_THREADS) sw3[idx] = g_w6c3[idx];
    if (t < 6) sb1[t] = g_bf1[t];
    if (t < 16) sb3[t] = g_bf3[t];
    for (int idx = t; idx < K12_IMG * 1296; idx += K12_THREADS) {
        int m = idx / 1296, p = idx % 1296;
        int r = p / 36, c = p % 36;
        int sr = min(max(r - 2, 0), 31);
        int sc = min(max(c - 2, 0), 31);
        sinb[m * 1296 + p] = x[(img0 + m) * 1024 + sr * 32 + sc];
    }
    __syncthreads();

    // ---- C1+S2+act ----
    {
        int pr = t >> 3;          // 0..47 = img*6 + ch
        int q = t & 7;
        int img = pr / 6, ch = pr % 6;
        float4 w4[9];
        float* w = (float*)w4;
        #pragma unroll
        for (int v = 0; v < 9; v++)
            w4[v] = ((const float4*)(sw1 + ch * 36))[v];
        float bias = sb1[ch];
        #pragma unroll
        for (int tl = 0; tl < 8; tl++) {
            // tile = q + tl*8 -> ti = tl, tj = q
            const float* bp = sinb + img * 1296 + (4 * tl) * 36 + 4 * q;
            float a00 = 0.f, a01 = 0.f, a10 = 0.f, a11 = 0.f;
            #pragma unroll
            for (int row = 0; row < 8; row++) {
                float2 rv2[4];
                float* rv = (float*)rv2;
                #pragma unroll
                for (int h = 0; h < 4; h++)
                    rv2[h] = *(const float2*)(bp + row * 36 + 2 * h);
                if (row < 6) {
                    #pragma unroll
                    for (int s = 0; s < 6; s++) {
                        float wv = w[row * 6 + s];
                        a00 = fmaf(wv, rv[s], a00);
                        a01 = fmaf(wv, rv[2 + s], a01);
                    }
                }
                if (row >= 2) {
                    #pragma unroll
                    for (int s = 0; s < 6; s++) {
                        float wv = w[(row - 2) * 6 + s];
                        a10 = fmaf(wv, rv[s], a10);
                        a11 = fmaf(wv, rv[2 + s], a11);
                    }
                }
            }
            float* op = sAb + img * 1536 + ch * 256 + (2 * tl) * 16 + 2 * q;
            op[0]  = ACT_SCALE * fast_tanh(a00 + bias);
            op[1]  = ACT_SCALE * fast_tanh(a01 + bias);
            op[16] = ACT_SCALE * fast_tanh(a10 + bias);
            op[17] = ACT_SCALE * fast_tanh(a11 + bias);
        }
    }
    __syncthreads();

    // ---- C3+S4+act (dense; masked weights are zero) ----
    {
        int pr = t / 3;           // 0..127 = img*16 + och
        int q = t % 3;
        int img = pr >> 4, och = pr & 15;
        float bias = sb3[och];
        float acc[3][4];
        #pragma unroll
        for (int u = 0; u < 3; u++)
            #pragma unroll
            for (int v = 0; v < 4; v++) acc[u][v] = 0.f;
        int ti_[3], tj_[3];
        #pragma unroll
        for (int u = 0; u < 3; u++) {
            int tile = q + u * 3;       // 0..8
            ti_[u] = tile / 3;
            tj_[u] = tile % 3;
        }
        for (int ic = 0; ic < 6; ic++) {
            float4 w4[9];
            float* w = (float*)w4;
            #pragma unroll
            for (int v = 0; v < 9; v++)
                w4[v] = ((const float4*)(sw3 + och * 216 + ic * 36))[v];
            #pragma unroll
            for (int u = 0; u < 3; u++) {
                const float* bp = sAb + img * 1536 + ic * 256 + (4 * ti_[u]) * 16 + 4 * tj_[u];
                #pragma unroll
                for (int row = 0; row < 8; row++) {
                    float2 rv2[4];
                    float* rv = (float*)rv2;
                    #pragma unroll
                    for (int h = 0; h < 4; h++)
                        rv2[h] = *(const float2*)(bp + row * 16 + 2 * h);
                    if (row < 6) {
                        #pragma unroll
                        for (int s = 0; s < 6; s++) {
                            float wv = w[row * 6 + s];
                            acc[u][0] = fmaf(wv, rv[s], acc[u][0]);
                            acc[u][1] = fmaf(wv, rv[2 + s], acc[u][1]);
                        }
                    }
                    if (row >= 2) {
                        #pragma unroll
                        for (int s = 0; s < 6; s++) {
                            float wv = w[(row - 2) * 6 + s];
                            acc[u][2] = fmaf(wv, rv[s], acc[u][2]);
                            acc[u][3] = fmaf(wv, rv[2 + s], acc[u][3]);
                        }
                    }
                }
            }
        }
        float* ob = g_B + (img0 + img) * 576 + och * 36;
        #pragma unroll
        for (int u = 0; u < 3; u++) {
            int r0 = 2 * ti_[u], c0 = 2 * tj_[u];
            ob[r0 * 6 + c0]           = ACT_SCALE * fast_tanh(acc[u][0] + bias);
            ob[r0 * 6 + c0 + 1]       = ACT_SCALE * fast_tanh(acc[u][1] + bias);
            ob[(r0 + 1) * 6 + c0]     = ACT_SCALE * fast_tanh(acc[u][2] + bias);
            ob[(r0 + 1) * 6 + c0 + 1] = ACT_SCALE * fast_tanh(acc[u][3] + bias);
        }
    }
}

// ---------------------------------------------------------------------------
// K3: C5 16->120 conv5x5 on 6x6 -> [2,2] positions (+bias).   (R6 version)
// 24 images/block (192 threads).  Weight chunk of 32 channels transposed in
// smem as [400][33] (pad 33 -> conflict-free).  Per in-channel the 6x6 input
// patch is cached in registers, then 25 k-steps of 16 FMAs.
// ---------------------------------------------------------------------------
#define K3_IMG 24
#define K3_CH  32
#define K3_THREADS 192
#define K3_INSTRIDE 584
#define K3_WSTRIDE  33
#define K3_SMEM ((K3_IMG * K3_INSTRIDE + 400 * K3_WSTRIDE) * 4)
#define K3_GRID ((8192 + K3_IMG - 1) / K3_IMG)

__global__ void __launch_bounds__(K3_THREADS) k3(const float* __restrict__ c5_w,
                                                 const float* __restrict__ c5_b) {
    extern __shared__ __align__(16) float sm3[];
    float* sin = sm3;                         // [24][584]
    float* swt = sm3 + K3_IMG * K3_INSTRIDE;  // [400][33] (k-major, ch minor)
    int t = threadIdx.x;
    long imgbase = (long)blockIdx.x * K3_IMG;
    for (int idx = t; idx < K3_IMG * 576; idx += K3_THREADS) {
        int im = idx / 576, off = idx % 576;
        long gi = imgbase + im;
        sin[im * K3_INSTRIDE + off] = (gi < 8192) ? g_B[gi * 576 + off] : 0.f;
    }
    int cg = t & 7;   // channel group (4 channels each)
    int pg = t >> 3;  // local image index 0..23
    const float* ip = sin + pg * K3_INSTRIDE;
    long gimg = imgbase + pg;
    float* outp = g_C + gimg * 480;

    for (int chunk = 0; chunk < 120; chunk += K3_CH) {
        __syncthreads();
        for (int idx = t; idx < K3_CH * 400; idx += K3_THREADS) {
            int ch = idx / 400, k = idx % 400;   // coalesced gmem read
            float wv = (chunk + ch < 120) ? c5_w[(long)(chunk + ch) * 400 + k] : 0.f;
            swt[k * K3_WSTRIDE + ch] = wv;       // conflict-free (33 is odd)
        }
        __syncthreads();

        float acc[4][4];
        #pragma unroll
        for (int p = 0; p < 4; p++)
            #pragma unroll
            for (int c = 0; c < 4; c++) acc[p][c] = 0.f;

        for (int ic = 0; ic < 16; ic++) {
            float4 pv4[9];
            float* pv = (float*)pv4;
            #pragma unroll
            for (int v = 0; v < 9; v++)
                pv4[v] = ((const float4*)(ip + ic * 36))[v];
            #pragma unroll
            for (int r = 0; r < 5; r++) {
                #pragma unroll
                for (int s = 0; s < 5; s++) {
                    const float* wk = swt + (ic * 25 + r * 5 + s) * K3_WSTRIDE + cg * 4;
                    float w0 = wk[0], w1 = wk[1], w2 = wk[2], w3 = wk[3];
                    #pragma unroll
                    for (int pi = 0; pi < 2; pi++)
                        #pragma unroll
                        for (int pj = 0; pj < 2; pj++) {
                            float v = pv[(pi + r) * 6 + pj + s];
                            int p = pi * 2 + pj;
                            acc[p][0] = fmaf(v, w0, acc[p][0]);
                            acc[p][1] = fmaf(v, w1, acc[p][1]);
                            acc[p][2] = fmaf(v, w2, acc[p][2]);
                            acc[p][3] = fmaf(v, w3, acc[p][3]);
                        }
                }
            }
        }
        if (gimg < 8192) {
            #pragma unroll
            for (int cc = 0; cc < 4; cc++) {
                int ch = chunk + cg * 4 + cc;
                if (ch < 120) {
                    float b = c5_b[ch];
                    float4 o;
                    o.x = acc[0][cc] + b;
                    o.y = acc[1][cc] + b;
                    o.z = acc[2][cc] + b;
                    o.w = acc[3][cc] + b;
                    *(float4*)(outp + ch * 4) = o;
                }
            }
        }
    }
}

// ---------------------------------------------------------------------------
// K4: F6 (120->84) + act + RBF.  View C as [32768][120]; 64 rows/block.
// Weights n-major [84][122] so k-pairs are adjacent; FFMA2 over k.
// sh overlays srow (after a barrier) -> smem 75.9 KB -> 3 CTAs/SM.
// ---------------------------------------------------------------------------
#define K4_ROWS 64
#define K4_SMEM ((K4_ROWS * 122 + 84 * 122 + 840 + 84) * 4)

__global__ void __launch_bounds__(256) k4(const float* __restrict__ f6_w,
                                          const float* __restrict__ f6_b,
                                          const float* __restrict__ rbf_w,
                                          float* __restrict__ out) {
    extern __shared__ __align__(16) float sm4[];
    float* srow = sm4;                   // [64][122]; later overlaid by sh [64][85]
    float* swt  = srow + K4_ROWS * 122;  // [84][122]  (n-major, pre-scaled)
    float* srbf = swt + 84 * 122;        // [84][10]
    float* sb6  = srbf + 840;            // [84]
    float* sh   = srow;                  // overlay
    int t = threadIdx.x, blk = blockIdx.x;
    long row0 = (long)blk * K4_ROWS;

    for (int idx = t; idx < K4_ROWS * 120; idx += 256) {
        int r = idx / 120, k = idx % 120;
        srow[r * 122 + k] = g_C[(row0 + r) * 120 + k];
    }
    for (int idx = t; idx < 84 * 120; idx += 256) {
        int n = idx / 120, k = idx % 120;
        swt[n * 122 + k] = ACT_SLOPE * f6_w[idx];
    }
    for (int idx = t; idx < 840; idx += 256) srbf[idx] = rbf_w[idx];
    if (t < 84) sb6[t] = ACT_SLOPE * f6_b[t];
    __syncthreads();

    int rg = t >> 4;    // 16 row-groups of 4 rows
    int cl = t & 15;    // column lane
    u64 acc[4][6];
    #pragma unroll
    for (int i = 0; i < 4; i++)
        #pragma unroll
        for (int q = 0; q < 6; q++) acc[i][q] = 0;

    const float* r0 = srow + (rg * 4 + 0) * 122;
    const float* r1 = srow + (rg * 4 + 1) * 122;
    const float* r2 = srow + (rg * 4 + 2) * 122;
    const float* r3 = srow + (rg * 4 + 3) * 122;
    for (int k = 0; k < 120; k += 2) {
        u64 v0 = *(const u64*)(r0 + k);
        u64 v1 = *(const u64*)(r1 + k);
        u64 v2 = *(const u64*)(r2 + k);
        u64 v3 = *(const u64*)(r3 + k);
        #pragma unroll
        for (int q = 0; q < 6; q++) {
            int n = cl + 16 * q;
            if (n < 84) {
                u64 w = *(const u64*)(swt + n * 122 + k);
                fma2(acc[0][q], v0, w);
                fma2(acc[1][q], v1, w);
                fma2(acc[2][q], v2, w);
                fma2(acc[3][q], v3, w);
            }
        }
    }
    float hv[4][6];
    #pragma unroll
    for (int q = 0; q < 6; q++) {
        int n = cl + 16 * q;
        if (n < 84) {
            float bias = sb6[n];
            #pragma unroll
            for (int i = 0; i < 4; i++)
                hv[i][q] = ACT_SCALE * fast_tanh(hsum2(acc[i][q]) + bias);
        }
    }
    __syncthreads();   // all reads of srow done before sh overlay writes
    #pragma unroll
    for (int q = 0; q < 6; q++) {
        int n = cl + 16 * q;
        if (n < 84) {
            #pragma unroll
            for (int i = 0; i < 4; i++)
                sh[(rg * 4 + i) * 85 + n] = hv[i][q];
        }
    }
    __syncthreads();

    for (int idx = t; idx < K4_ROWS * 10; idx += 256) {
        int r = idx / 10, o = idx % 10;
        const float* hr = sh + r * 85;
        float s = 0.f;
        #pragma unroll 4
        for (int n = 0; n < 84; n++) {
            float d = hr[n] - srbf[n * 10 + o];
            s = fmaf(d, d, s);
        }
        out[(row0 + r) * 10 + o] = s;
    }
}

// ---------------------------------------------------------------------------
extern "C" void kernel_launch(void* const* d_in, const int* in_sizes, int n_in,
                              void* d_out, int out_size) {
    const float* x     = (const float*)d_in[0];
    const float* c1_w  = (const float*)d_in[1];
    const float* c1_b  = (const float*)d_in[2];
    const float* s2_w  = (const float*)d_in[3];
    const float* s2_b  = (const float*)d_in[4];
    const float* c3_w  = (const float*)d_in[5];
    const float* c3_b  = (const float*)d_in[6];
    const float* s4_w  = (const float*)d_in[7];
    const float* s4_b  = (const float*)d_in[8];
    const float* c5_w  = (const float*)d_in[9];
    const float* c5_b  = (const float*)d_in[10];
    const float* f6_w  = (const float*)d_in[11];
    const float* f6_b  = (const float*)d_in[12];
    const float* rbf_w = (const float*)d_in[13];

    cudaFuncSetAttribute(k12, cudaFuncAttributeMaxDynamicSharedMemorySize, K12_SMEM);
    cudaFuncSetAttribute(k3, cudaFuncAttributeMaxDynamicSharedMemorySize, K3_SMEM);
    cudaFuncSetAttribute(k4, cudaFuncAttributeMaxDynamicSharedMemorySize, K4_SMEM);

    k_prep<<<1, 256>>>(c1_w, c1_b, s2_w, s2_b, c3_w, c3_b, s4_w, s4_b);
    k12<<<8192 / K12_IMG, K12_THREADS, K12_SMEM>>>(x);
    k3<<<K3_GRID, K3_THREADS, K3_SMEM>>>(c5_w, c5_b);
    k4<<<32768 / K4_ROWS, 256, K4_SMEM>>>(f6_w, f6_b, rbf_w, (float*)d_out);
}